// round 1
// baseline (speedup 1.0000x reference)
#include <cuda_runtime.h>
#include <math_constants.h>
#include <cstdint>

#define BB 4
#define TT 2048
#define CC 1024
#define HH 128

// scratch for q, k, v projections: [B, T, H] each (4 MB each)
__device__ float g_q[BB * TT * HH];
__device__ float g_k[BB * TT * HH];
__device__ float g_v[BB * TT * HH];

// ---------------------------------------------------------------------------
// Projection GEMM: out[m, h] = sum_c x[m, c] * W[c, h]
// M = B*T = 8192, K = C = 1024, N = H = 128.
// Tile: 64 (M) x 128 (N), BK = 16. 256 threads; each thread: 4 rows x 8 cols.
// Row assignment: ty + 16*rr (broadcast reads of As across tx).
// Col assignment: tx + 16*i  (conflict-free Bs reads: bank = tx).
// ---------------------------------------------------------------------------
__global__ __launch_bounds__(256) void proj_kernel(
    const float* __restrict__ x,
    const float* __restrict__ Wq,
    const float* __restrict__ Wk,
    const float* __restrict__ Wv)
{
    __shared__ float As[64 * 17];    // [row][k], stride 17
    __shared__ float Bs[16 * 132];   // [k][col], stride 132 (16B-aligned pad)

    const float* W;
    float* dst;
    if (blockIdx.y == 0)      { W = Wq; dst = g_q; }
    else if (blockIdx.y == 1) { W = Wk; dst = g_k; }
    else                      { W = Wv; dst = g_v; }

    const int tid = threadIdx.x;
    const int tx = tid & 15;
    const int ty = tid >> 4;
    const int m0 = blockIdx.x * 64;

    // loader indices
    const int lr  = tid >> 2;        // 0..63 : row of x tile
    const int lkq = (tid & 3) * 4;   // k-quad within 16
    const int wkk = tid >> 4;        // 0..15 : row of W tile
    const int wc8 = (tid & 15) * 8;  // col8 of W tile

    float acc[4][8];
#pragma unroll
    for (int r = 0; r < 4; r++)
#pragma unroll
        for (int i = 0; i < 8; i++) acc[r][i] = 0.f;

    for (int k0 = 0; k0 < CC; k0 += 16) {
        __syncthreads();
        // load x tile 64x16
        float4 xa = *(const float4*)(x + (size_t)(m0 + lr) * CC + k0 + lkq);
        As[lr * 17 + lkq + 0] = xa.x;
        As[lr * 17 + lkq + 1] = xa.y;
        As[lr * 17 + lkq + 2] = xa.z;
        As[lr * 17 + lkq + 3] = xa.w;
        // load W tile 16x128
        float4 w0 = *(const float4*)(W + (size_t)(k0 + wkk) * HH + wc8);
        float4 w1 = *(const float4*)(W + (size_t)(k0 + wkk) * HH + wc8 + 4);
        *(float4*)(Bs + wkk * 132 + wc8)     = w0;
        *(float4*)(Bs + wkk * 132 + wc8 + 4) = w1;
        __syncthreads();

#pragma unroll
        for (int kk = 0; kk < 16; kk++) {
            float a[4], b[8];
#pragma unroll
            for (int r = 0; r < 4; r++) a[r] = As[(ty + 16 * r) * 17 + kk];
#pragma unroll
            for (int i = 0; i < 8; i++) b[i] = Bs[kk * 132 + tx + 16 * i];
#pragma unroll
            for (int r = 0; r < 4; r++)
#pragma unroll
                for (int i = 0; i < 8; i++)
                    acc[r][i] = fmaf(a[r], b[i], acc[r][i]);
        }
    }

#pragma unroll
    for (int r = 0; r < 4; r++) {
        const int row = m0 + ty + 16 * r;
#pragma unroll
        for (int i = 0; i < 8; i++)
            dst[(size_t)row * HH + tx + 16 * i] = acc[r][i];
    }
}

// ---------------------------------------------------------------------------
// Flash attention: per block = 64 queries of one batch; loop 64-key tiles
// with online softmax. 256 threads.
//   S fragment: 4 rows (ty+16rr) x 4 key-cols (tx+16cc)
//   O fragment: 4 rows x 8 head-cols (tx+16i)
// smem: Qs[64][132], KVs[64][132] (K then V per tile), Ss[64][65]
// ---------------------------------------------------------------------------
#define ATT_SMEM_FLOATS (64 * 132 * 2 + 64 * 65)

__global__ __launch_bounds__(256) void attn_kernel(float* __restrict__ out)
{
    extern __shared__ float sm[];
    float* Qs  = sm;                 // 64*132
    float* KVs = sm + 64 * 132;      // 64*132
    float* Ss  = sm + 2 * 64 * 132;  // 64*65

    __shared__ float m_sh[64];
    __shared__ float l_sh[64];
    __shared__ float f_sh[64];
    __shared__ float red[64 * 4];

    const int tid = threadIdx.x;
    const int tx = tid & 15;
    const int ty = tid >> 4;
    const int qt = blockIdx.x;       // query tile
    const int b  = blockIdx.y;       // batch

    const float* qp = g_q + (size_t)b * TT * HH;
    const float* kp = g_k + (size_t)b * TT * HH;
    const float* vp = g_v + (size_t)b * TT * HH;

    const int lr   = tid >> 2;       // 0..63 tile-load row
    const int lc0  = (tid & 3) * 32; // col base (8 float4s)
    const int r0 = qt * 64;

    // load Q tile
#pragma unroll
    for (int u = 0; u < 8; u++) {
        const int c = lc0 + 4 * u;
        *(float4*)(Qs + lr * 132 + c) =
            *(const float4*)(qp + (size_t)(r0 + lr) * HH + c);
    }
    if (tid < 64) { m_sh[tid] = -CUDART_INF_F; l_sh[tid] = 0.f; }

    float acc[4][8];
#pragma unroll
    for (int r = 0; r < 4; r++)
#pragma unroll
        for (int i = 0; i < 8; i++) acc[r][i] = 0.f;

    const float inv_scale = 0.03125f;  // C^-0.5 = 1/32 (NOT H^-0.5)

    for (int jt = 0; jt <= qt; jt++) {
        const int j0 = jt * 64;
        __syncthreads();  // KVs free (prev PV done); Qs ready on first iter
        // load K tile
#pragma unroll
        for (int u = 0; u < 8; u++) {
            const int c = lc0 + 4 * u;
            *(float4*)(KVs + lr * 132 + c) =
                *(const float4*)(kp + (size_t)(j0 + lr) * HH + c);
        }
        __syncthreads();

        // S = Q K^T (4x4 fragment)
        float s[4][4];
#pragma unroll
        for (int r = 0; r < 4; r++)
#pragma unroll
            for (int c2 = 0; c2 < 4; c2++) s[r][c2] = 0.f;

#pragma unroll 4
        for (int h = 0; h < HH; h += 4) {
            float4 q4[4], k4[4];
#pragma unroll
            for (int r = 0; r < 4; r++)
                q4[r] = *(const float4*)(Qs + (ty + 16 * r) * 132 + h);
#pragma unroll
            for (int c2 = 0; c2 < 4; c2++)
                k4[c2] = *(const float4*)(KVs + (tx + 16 * c2) * 132 + h);
#pragma unroll
            for (int r = 0; r < 4; r++)
#pragma unroll
                for (int c2 = 0; c2 < 4; c2++) {
                    s[r][c2] = fmaf(q4[r].x, k4[c2].x, s[r][c2]);
                    s[r][c2] = fmaf(q4[r].y, k4[c2].y, s[r][c2]);
                    s[r][c2] = fmaf(q4[r].z, k4[c2].z, s[r][c2]);
                    s[r][c2] = fmaf(q4[r].w, k4[c2].w, s[r][c2]);
                }
        }

        // scale + causal mask, store to Ss
#pragma unroll
        for (int r = 0; r < 4; r++) {
            const int rg = r0 + ty + 16 * r;
#pragma unroll
            for (int c2 = 0; c2 < 4; c2++) {
                const int jg = j0 + tx + 16 * c2;
                float v = s[r][c2] * inv_scale;
                if (jg > rg) v = -CUDART_INF_F;
                Ss[(ty + 16 * r) * 65 + tx + 16 * c2] = v;
            }
        }
        __syncthreads();  // Ss ready; K reads done

        // prefetch V tile into KVs (overlaps with softmax below)
#pragma unroll
        for (int u = 0; u < 8; u++) {
            const int c = lc0 + 4 * u;
            *(float4*)(KVs + lr * 132 + c) =
                *(const float4*)(vp + (size_t)(j0 + lr) * HH + c);
        }

        // softmax phase 1: per-row partial max (4 threads per row)
        {
            const int r = tid >> 2, part = tid & 3;
            float mx = -CUDART_INF_F;
#pragma unroll
            for (int k2 = 0; k2 < 16; k2++)
                mx = fmaxf(mx, Ss[r * 65 + part * 16 + k2]);
            red[r * 4 + part] = mx;
        }
        __syncthreads();
        if (tid < 64) {
            const float mo = m_sh[tid];
            float mn = fmaxf(fmaxf(red[tid * 4 + 0], red[tid * 4 + 1]),
                             fmaxf(red[tid * 4 + 2], red[tid * 4 + 3]));
            mn = fmaxf(mo, mn);
            m_sh[tid] = mn;
            f_sh[tid] = __expf(mo - mn);
        }
        __syncthreads();

        // softmax phase 2: exp, partial row sums; rescale O accumulators
        {
            const int r = tid >> 2, part = tid & 3;
            const float mrow = m_sh[r];
            float ssum = 0.f;
#pragma unroll
            for (int k2 = 0; k2 < 16; k2++) {
                const int idx = r * 65 + part * 16 + k2;
                const float p = __expf(Ss[idx] - mrow);
                Ss[idx] = p;
                ssum += p;
            }
            red[r * 4 + part] = ssum;
        }
#pragma unroll
        for (int r = 0; r < 4; r++) {
            const float f = f_sh[ty + 16 * r];
#pragma unroll
            for (int i = 0; i < 8; i++) acc[r][i] *= f;
        }
        __syncthreads();  // Ss (probs) + V in KVs ready for PV

        if (tid < 64) {
            l_sh[tid] = l_sh[tid] * f_sh[tid] +
                        red[tid * 4 + 0] + red[tid * 4 + 1] +
                        red[tid * 4 + 2] + red[tid * 4 + 3];
        }

        // O += P @ V
#pragma unroll 2
        for (int j = 0; j < 64; j++) {
            float p[4], v[8];
#pragma unroll
            for (int r = 0; r < 4; r++)
                p[r] = Ss[(ty + 16 * r) * 65 + j];
#pragma unroll
            for (int i = 0; i < 8; i++)
                v[i] = KVs[j * 132 + tx + 16 * i];
#pragma unroll
            for (int r = 0; r < 4; r++)
#pragma unroll
                for (int i = 0; i < 8; i++)
                    acc[r][i] = fmaf(p[r], v[i], acc[r][i]);
        }
    }

    __syncthreads();  // last l_sh update visible

#pragma unroll
    for (int r = 0; r < 4; r++) {
        const int row = r0 + ty + 16 * r;
        const float inv_l = 1.f / l_sh[ty + 16 * r];
#pragma unroll
        for (int i = 0; i < 8; i++)
            out[(size_t)b * TT * HH + (size_t)row * HH + tx + 16 * i] =
                acc[r][i] * inv_l;
    }
}

// ---------------------------------------------------------------------------
extern "C" void kernel_launch(void* const* d_in, const int* in_sizes, int n_in,
                              void* d_out, int out_size)
{
    (void)in_sizes; (void)n_in; (void)out_size;
    const float* x  = (const float*)d_in[0];
    const float* Wq = (const float*)d_in[1];
    const float* Wk = (const float*)d_in[2];
    const float* Wv = (const float*)d_in[3];
    // d_in[4] = mask (int32) — causal mask computed analytically, unused.
    float* out = (float*)d_out;

    // projections: 8192/64 = 128 row-tiles x 3 weights
    dim3 pgrid(TT * BB / 64, 3);
    proj_kernel<<<pgrid, 256>>>(x, Wq, Wk, Wv);

    // attention
    const int smem_bytes = ATT_SMEM_FLOATS * (int)sizeof(float);  // 84224
    cudaFuncSetAttribute(attn_kernel,
                         cudaFuncAttributeMaxDynamicSharedMemorySize,
                         smem_bytes);
    dim3 agrid(TT / 64, BB);
    attn_kernel<<<agrid, 256, smem_bytes>>>(out);
}

// round 2
// speedup vs baseline: 1.5504x; 1.5504x over previous
#include <cuda_runtime.h>
#include <math_constants.h>
#include <cstdint>

#define BB 4
#define TT 2048
#define CC 1024
#define HH 128

// scratch: q,k,v projections [B,T,H]
__device__ float g_q[BB * TT * HH];
__device__ float g_k[BB * TT * HH];
__device__ float g_v[BB * TT * HH];

// attention partials: [B][32 qtiles][4 chunks]
__device__ float g_po[BB * 32 * 4 * 64 * HH];
__device__ float g_pm[BB * 32 * 4 * 64];
__device__ float g_pl[BB * 32 * 4 * 64];

// ---------------------------------------------------------------------------
// tf32 helpers
// ---------------------------------------------------------------------------
__device__ __forceinline__ uint32_t f2tf(float x) {
    uint32_t r;
    asm("cvt.rna.tf32.f32 %0, %1;" : "=r"(r) : "f"(x));
    return r;
}

__device__ __forceinline__ void mma_tf32(float c[4],
                                         uint32_t a0, uint32_t a1,
                                         uint32_t a2, uint32_t a3,
                                         uint32_t b0, uint32_t b1) {
    asm volatile(
        "mma.sync.aligned.m16n8k8.row.col.f32.tf32.tf32.f32 "
        "{%0,%1,%2,%3}, {%4,%5,%6,%7}, {%8,%9}, {%0,%1,%2,%3};"
        : "+f"(c[0]), "+f"(c[1]), "+f"(c[2]), "+f"(c[3])
        : "r"(a0), "r"(a1), "r"(a2), "r"(a3), "r"(b0), "r"(b1));
}

// ---------------------------------------------------------------------------
// Projection GEMM via tf32 mma.sync, 3xTF32 split (hi*hi + hi*lo + lo*hi).
// out[m,h] = sum_c x[m,c] * W[c,h].  M=8192, K=1024, N=128.
// Block: 64 (M) x 128 (N), BK=32, 256 threads = 8 warps (2 Mwarps x 4 Nwarps),
// each warp 32x32, = 2x4 m16n8k8 tiles.
// Smem strides chosen for conflict-free fragment loads:
//   X stride 36 (36 mod 32 == 4 -> bank = 4*g + tg, all distinct)
//   W stride 136 (136 mod 32 == 8 -> bank = 8*tg + g, all distinct)
// ---------------------------------------------------------------------------
#define XS 36
#define WS 136
#define PROJ_SMEM_U32 (2 * 64 * XS + 2 * 32 * WS)   // 13312 u32 = 53248 B

__global__ __launch_bounds__(256) void proj_kernel(
    const float* __restrict__ x,
    const float* __restrict__ Wq,
    const float* __restrict__ Wk,
    const float* __restrict__ Wv)
{
    extern __shared__ uint32_t psm[];
    uint32_t* Xh = psm;                 // 64*XS
    uint32_t* Xl = Xh + 64 * XS;
    uint32_t* Wh = Xl + 64 * XS;        // 32*WS
    uint32_t* Wl = Wh + 32 * WS;

    const float* W;
    float* dst;
    if (blockIdx.y == 0)      { W = Wq; dst = g_q; }
    else if (blockIdx.y == 1) { W = Wk; dst = g_k; }
    else                      { W = Wv; dst = g_v; }

    const int tid  = threadIdx.x;
    const int lane = tid & 31;
    const int wid  = tid >> 5;
    const int wm   = wid & 1;        // warp row (2)
    const int wn   = wid >> 1;       // warp col (4)
    const int g    = lane >> 2;      // group id 0..7
    const int tg   = lane & 3;       // thread in group 0..3
    const int m0   = blockIdx.x * 64;

    // loader indices
    const int xrow = tid >> 2;           // 0..63
    const int xkq  = (tid & 3) * 8;      // 0,8,16,24
    const int wrow = tid >> 3;           // 0..31
    const int wcb  = (tid & 7) * 16;     // 0..112

    float acc[2][4][4];
#pragma unroll
    for (int mt = 0; mt < 2; mt++)
#pragma unroll
        for (int nt = 0; nt < 4; nt++)
#pragma unroll
            for (int i = 0; i < 4; i++) acc[mt][nt][i] = 0.f;

    for (int k0 = 0; k0 < CC; k0 += 32) {
        __syncthreads();
        // X tile 64x32 -> hi/lo
#pragma unroll
        for (int u = 0; u < 2; u++) {
            float4 xv = *(const float4*)(x + (size_t)(m0 + xrow) * CC + k0 + xkq + 4 * u);
            const float vv[4] = {xv.x, xv.y, xv.z, xv.w};
#pragma unroll
            for (int j = 0; j < 4; j++) {
                uint32_t h = f2tf(vv[j]);
                float lo = vv[j] - __uint_as_float(h);
                Xh[xrow * XS + xkq + 4 * u + j] = h;
                Xl[xrow * XS + xkq + 4 * u + j] = f2tf(lo);
            }
        }
        // W tile 32x128 -> hi/lo
#pragma unroll
        for (int u = 0; u < 4; u++) {
            float4 wv = *(const float4*)(W + (size_t)(k0 + wrow) * HH + wcb + 4 * u);
            const float vv[4] = {wv.x, wv.y, wv.z, wv.w};
#pragma unroll
            for (int j = 0; j < 4; j++) {
                uint32_t h = f2tf(vv[j]);
                float lo = vv[j] - __uint_as_float(h);
                Wh[wrow * WS + wcb + 4 * u + j] = h;
                Wl[wrow * WS + wcb + 4 * u + j] = f2tf(lo);
            }
        }
        __syncthreads();

#pragma unroll
        for (int ks = 0; ks < 4; ks++) {
            const int kb = ks * 8;
            uint32_t ah[2][4], al[2][4];
#pragma unroll
            for (int mt = 0; mt < 2; mt++) {
                const int r0 = wm * 32 + mt * 16;
                ah[mt][0] = Xh[(r0 + g)     * XS + kb + tg];
                ah[mt][1] = Xh[(r0 + g + 8) * XS + kb + tg];
                ah[mt][2] = Xh[(r0 + g)     * XS + kb + tg + 4];
                ah[mt][3] = Xh[(r0 + g + 8) * XS + kb + tg + 4];
                al[mt][0] = Xl[(r0 + g)     * XS + kb + tg];
                al[mt][1] = Xl[(r0 + g + 8) * XS + kb + tg];
                al[mt][2] = Xl[(r0 + g)     * XS + kb + tg + 4];
                al[mt][3] = Xl[(r0 + g + 8) * XS + kb + tg + 4];
            }
            uint32_t bh[4][2], bl[4][2];
#pragma unroll
            for (int nt = 0; nt < 4; nt++) {
                const int c0 = wn * 32 + nt * 8 + g;
                bh[nt][0] = Wh[(kb + tg)     * WS + c0];
                bh[nt][1] = Wh[(kb + tg + 4) * WS + c0];
                bl[nt][0] = Wl[(kb + tg)     * WS + c0];
                bl[nt][1] = Wl[(kb + tg + 4) * WS + c0];
            }
#pragma unroll
            for (int mt = 0; mt < 2; mt++)
#pragma unroll
                for (int nt = 0; nt < 4; nt++) {
                    mma_tf32(acc[mt][nt], ah[mt][0], ah[mt][1], ah[mt][2], ah[mt][3],
                             bh[nt][0], bh[nt][1]);
                    mma_tf32(acc[mt][nt], ah[mt][0], ah[mt][1], ah[mt][2], ah[mt][3],
                             bl[nt][0], bl[nt][1]);
                    mma_tf32(acc[mt][nt], al[mt][0], al[mt][1], al[mt][2], al[mt][3],
                             bh[nt][0], bh[nt][1]);
                }
        }
    }

    // epilogue
#pragma unroll
    for (int mt = 0; mt < 2; mt++) {
        const int rbase = m0 + wm * 32 + mt * 16;
#pragma unroll
        for (int nt = 0; nt < 4; nt++) {
            const int col = wn * 32 + nt * 8 + 2 * tg;
            *(float2*)(dst + (size_t)(rbase + g) * HH + col) =
                make_float2(acc[mt][nt][0], acc[mt][nt][1]);
            *(float2*)(dst + (size_t)(rbase + g + 8) * HH + col) =
                make_float2(acc[mt][nt][2], acc[mt][nt][3]);
        }
    }
}

// ---------------------------------------------------------------------------
// Flash attention, split-KV balanced: block = (qtile, batch, chunk).
// chunk c covers key tiles [8c, min(8c+8, qt+1)); invalid chunks exit.
// Writes unnormalized partial O + (m, l); combine kernel merges.
// ---------------------------------------------------------------------------
#define ATT_SMEM_FLOATS (64 * 132 * 2 + 64 * 65)

__global__ __launch_bounds__(256, 2) void attn_kernel()
{
    const int qt = blockIdx.x;       // 0..31
    const int b  = blockIdx.y;       // 0..3
    const int ch = blockIdx.z;       // 0..3
    if (ch * 8 > qt) return;         // invalid chunk

    extern __shared__ float sm[];
    float* Qs  = sm;                 // 64*132
    float* KVs = sm + 64 * 132;      // 64*132
    float* Ss  = sm + 2 * 64 * 132;  // 64*65

    __shared__ float m_sh[64];
    __shared__ float l_sh[64];
    __shared__ float f_sh[64];
    __shared__ float red[64 * 4];

    const int tid = threadIdx.x;
    const int tx = tid & 15;
    const int ty = tid >> 4;

    const float* qp = g_q + (size_t)b * TT * HH;
    const float* kp = g_k + (size_t)b * TT * HH;
    const float* vp = g_v + (size_t)b * TT * HH;

    const int lr  = tid >> 2;
    const int lc0 = (tid & 3) * 32;
    const int r0  = qt * 64;

    // load Q tile
#pragma unroll
    for (int u = 0; u < 8; u++) {
        const int c = lc0 + 4 * u;
        *(float4*)(Qs + lr * 132 + c) =
            *(const float4*)(qp + (size_t)(r0 + lr) * HH + c);
    }
    if (tid < 64) { m_sh[tid] = -CUDART_INF_F; l_sh[tid] = 0.f; }

    float acc[4][8];
#pragma unroll
    for (int r = 0; r < 4; r++)
#pragma unroll
        for (int i = 0; i < 8; i++) acc[r][i] = 0.f;

    const float inv_scale = 0.03125f;  // C^-0.5 = 1/32

    const int jt0 = ch * 8;
    const int jt1 = min(jt0 + 8, qt + 1);

    for (int jt = jt0; jt < jt1; jt++) {
        const int j0 = jt * 64;
        __syncthreads();
#pragma unroll
        for (int u = 0; u < 8; u++) {
            const int c = lc0 + 4 * u;
            *(float4*)(KVs + lr * 132 + c) =
                *(const float4*)(kp + (size_t)(j0 + lr) * HH + c);
        }
        __syncthreads();

        // S = Q K^T
        float s[4][4];
#pragma unroll
        for (int r = 0; r < 4; r++)
#pragma unroll
            for (int c2 = 0; c2 < 4; c2++) s[r][c2] = 0.f;

#pragma unroll 4
        for (int h = 0; h < HH; h += 4) {
            float4 q4[4], k4[4];
#pragma unroll
            for (int r = 0; r < 4; r++)
                q4[r] = *(const float4*)(Qs + (ty + 16 * r) * 132 + h);
#pragma unroll
            for (int c2 = 0; c2 < 4; c2++)
                k4[c2] = *(const float4*)(KVs + (tx + 16 * c2) * 132 + h);
#pragma unroll
            for (int r = 0; r < 4; r++)
#pragma unroll
                for (int c2 = 0; c2 < 4; c2++) {
                    s[r][c2] = fmaf(q4[r].x, k4[c2].x, s[r][c2]);
                    s[r][c2] = fmaf(q4[r].y, k4[c2].y, s[r][c2]);
                    s[r][c2] = fmaf(q4[r].z, k4[c2].z, s[r][c2]);
                    s[r][c2] = fmaf(q4[r].w, k4[c2].w, s[r][c2]);
                }
        }

        // scale (+ mask only on the diagonal tile), store to Ss
        if (jt == qt) {
#pragma unroll
            for (int r = 0; r < 4; r++) {
                const int rg = r0 + ty + 16 * r;
#pragma unroll
                for (int c2 = 0; c2 < 4; c2++) {
                    const int jg = j0 + tx + 16 * c2;
                    float v = s[r][c2] * inv_scale;
                    if (jg > rg) v = -CUDART_INF_F;
                    Ss[(ty + 16 * r) * 65 + tx + 16 * c2] = v;
                }
            }
        } else {
#pragma unroll
            for (int r = 0; r < 4; r++)
#pragma unroll
                for (int c2 = 0; c2 < 4; c2++)
                    Ss[(ty + 16 * r) * 65 + tx + 16 * c2] = s[r][c2] * inv_scale;
        }
        __syncthreads();

        // prefetch V (overlaps softmax)
#pragma unroll
        for (int u = 0; u < 8; u++) {
            const int c = lc0 + 4 * u;
            *(float4*)(KVs + lr * 132 + c) =
                *(const float4*)(vp + (size_t)(j0 + lr) * HH + c);
        }

        // row max partials
        {
            const int r = tid >> 2, part = tid & 3;
            float mx = -CUDART_INF_F;
#pragma unroll
            for (int k2 = 0; k2 < 16; k2++)
                mx = fmaxf(mx, Ss[r * 65 + part * 16 + k2]);
            red[r * 4 + part] = mx;
        }
        __syncthreads();
        if (tid < 64) {
            const float mo = m_sh[tid];
            float mn = fmaxf(fmaxf(red[tid * 4 + 0], red[tid * 4 + 1]),
                             fmaxf(red[tid * 4 + 2], red[tid * 4 + 3]));
            mn = fmaxf(mo, mn);
            m_sh[tid] = mn;
            f_sh[tid] = __expf(mo - mn);
        }
        __syncthreads();

        // exp + row-sum partials; rescale O
        {
            const int r = tid >> 2, part = tid & 3;
            const float mrow = m_sh[r];
            float ssum = 0.f;
#pragma unroll
            for (int k2 = 0; k2 < 16; k2++) {
                const int idx = r * 65 + part * 16 + k2;
                const float p = __expf(Ss[idx] - mrow);
                Ss[idx] = p;
                ssum += p;
            }
            red[r * 4 + part] = ssum;
        }
#pragma unroll
        for (int r = 0; r < 4; r++) {
            const float f = f_sh[ty + 16 * r];
#pragma unroll
            for (int i = 0; i < 8; i++) acc[r][i] *= f;
        }
        __syncthreads();

        if (tid < 64) {
            l_sh[tid] = l_sh[tid] * f_sh[tid] +
                        red[tid * 4 + 0] + red[tid * 4 + 1] +
                        red[tid * 4 + 2] + red[tid * 4 + 3];
        }

        // O += P @ V
#pragma unroll 2
        for (int j = 0; j < 64; j++) {
            float p[4], v[8];
#pragma unroll
            for (int r = 0; r < 4; r++)
                p[r] = Ss[(ty + 16 * r) * 65 + j];
#pragma unroll
            for (int i = 0; i < 8; i++)
                v[i] = KVs[j * 132 + tx + 16 * i];
#pragma unroll
            for (int r = 0; r < 4; r++)
#pragma unroll
                for (int i = 0; i < 8; i++)
                    acc[r][i] = fmaf(p[r], v[i], acc[r][i]);
        }
    }

    __syncthreads();

    // write unnormalized partial + (m, l)
    const size_t pbase = ((size_t)(b * 32 + qt) * 4 + ch);
    float* po = g_po + pbase * 64 * HH;
#pragma unroll
    for (int r = 0; r < 4; r++)
#pragma unroll
        for (int i = 0; i < 8; i++)
            po[(size_t)(ty + 16 * r) * HH + tx + 16 * i] = acc[r][i];
    if (tid < 64) {
        g_pm[pbase * 64 + tid] = m_sh[tid];
        g_pl[pbase * 64 + tid] = l_sh[tid];
    }
}

// ---------------------------------------------------------------------------
// Combine partials: out = (sum_c e^{m_c - M} O_c) / (sum_c e^{m_c - M} l_c)
// ---------------------------------------------------------------------------
__global__ __launch_bounds__(256) void combine_kernel(float* __restrict__ out)
{
    const int qt = blockIdx.x;
    const int b  = blockIdx.y;
    const int nc = (qt + 8) >> 3;   // number of chunks for this qtile

    const int tid = threadIdx.x;
    const int r  = tid >> 2;        // 0..63
    const int cb = (tid & 3) * 32;  // 0,32,64,96

    const size_t pbase = (size_t)(b * 32 + qt) * 4;

    float M = -CUDART_INF_F;
    for (int c = 0; c < nc; c++)
        M = fmaxf(M, g_pm[(pbase + c) * 64 + r]);

    float w[4];
    float l = 0.f;
    for (int c = 0; c < nc; c++) {
        w[c] = __expf(g_pm[(pbase + c) * 64 + r] - M);
        l += w[c] * g_pl[(pbase + c) * 64 + r];
    }
    const float inv = 1.f / l;

    float* op = out + ((size_t)b * TT + qt * 64 + r) * HH;
#pragma unroll
    for (int u = 0; u < 8; u++) {
        float ox = 0.f, oy = 0.f, oz = 0.f, ow = 0.f;
        for (int c = 0; c < nc; c++) {
            const float4 p = *(const float4*)(g_po +
                ((pbase + c) * 64 + r) * HH + cb + 4 * u);
            ox += w[c] * p.x; oy += w[c] * p.y;
            oz += w[c] * p.z; ow += w[c] * p.w;
        }
        *(float4*)(op + cb + 4 * u) =
            make_float4(ox * inv, oy * inv, oz * inv, ow * inv);
    }
}

// ---------------------------------------------------------------------------
extern "C" void kernel_launch(void* const* d_in, const int* in_sizes, int n_in,
                              void* d_out, int out_size)
{
    (void)in_sizes; (void)n_in; (void)out_size;
    const float* x  = (const float*)d_in[0];
    const float* Wq = (const float*)d_in[1];
    const float* Wk = (const float*)d_in[2];
    const float* Wv = (const float*)d_in[3];
    float* out = (float*)d_out;

    const int proj_smem = PROJ_SMEM_U32 * (int)sizeof(uint32_t);  // 53248
    cudaFuncSetAttribute(proj_kernel,
                         cudaFuncAttributeMaxDynamicSharedMemorySize,
                         proj_smem);
    dim3 pgrid(TT * BB / 64, 3);
    proj_kernel<<<pgrid, 256, proj_smem>>>(x, Wq, Wk, Wv);

    const int attn_smem = ATT_SMEM_FLOATS * (int)sizeof(float);   // 84224
    cudaFuncSetAttribute(attn_kernel,
                         cudaFuncAttributeMaxDynamicSharedMemorySize,
                         attn_smem);
    dim3 agrid(32, BB, 4);
    attn_kernel<<<agrid, 256, attn_smem>>>();

    dim3 cgrid(32, BB);
    combine_kernel<<<cgrid, 256>>>(out);
}